// round 2
// baseline (speedup 1.0000x reference)
#include <cuda_runtime.h>
#include <math.h>
#include <stdint.h>
#include <stddef.h>

#define N_    4096
#define SEQ_  41
#define VEC_  15
#define TT_   8
#define EMB_  32
#define LDIM_ 256
#define RED_  64
#define M_TOT (N_*SEQ_)
#define EPS_  1e-5f

// ---------------- scratch (__device__ globals; no allocation allowed) ------
__device__ float  g_h[N_*EMB_];
__device__ float  g_mu[EMB_], g_rvar[EMB_];
__device__ float  g_emb[N_*EMB_];
__device__ float  g_sqn[N_];
__device__ float  g_D[(size_t)N_*N_];                 // 64 MB
__device__ float  g_dpart[4096];
__device__ float  g_avg;
__device__ float  g_pmin[1024], g_pmax[1024];
__device__ float  g_mn, g_scale;
__device__ float  g_U[(size_t)M_TOT*192];             // 129 MB: L @ [Wp1|Wq1|Wa]
__device__ float  g_pos[N_*RED_], g_neg[N_*RED_];
__device__ float  g_psqn[N_], g_nsqn[N_];
__device__ float  g_zconst[2*RED_];
__device__ double g_spartA[4096], g_spartB[4096];

// ---------------- K1: interpolate key regions + h = tanh(flat@W1+b1) -------
__global__ void k_interp_h(const float* __restrict__ A, const int* __restrict__ C,
                           const float* __restrict__ W1, const float* __restrict__ b1) {
    int n = blockIdx.x;
    __shared__ float sflat[TT_*VEC_];
    __shared__ int   si0[TT_], si1[TT_];
    __shared__ float sw[TT_];
    __shared__ int   sstart;
    int tid = threadIdx.x;
    if (tid == 0) sstart = C[2*n];
    if (tid < TT_) {
        int start = C[2*n], end = C[2*n+1];
        int length = end - start + 1;
        float scale = (float)length / (float)TT_;
        float src = scale * ((float)tid + 0.5f) - 0.5f;
        src = fmaxf(src, 0.f);
        int i0 = (int)floorf(src);
        if (i0 > length-1) i0 = length-1;
        int i1 = i0 + 1; if (i1 > length-1) i1 = length-1;
        si0[tid] = i0; si1[tid] = i1;
        sw[tid] = src - (float)i0;
    }
    __syncthreads();
    int start = sstart;
    const float* Ar = A + (size_t)n*SEQ_*VEC_;
    for (int idx = tid; idx < TT_*VEC_; idx += blockDim.x) {
        int t = idx / VEC_, v = idx % VEC_;
        float g0 = Ar[(start+si0[t])*VEC_ + v];
        float g1 = Ar[(start+si1[t])*VEC_ + v];
        float w  = sw[t];
        sflat[idx] = (1.f - w)*g0 + w*g1;
    }
    __syncthreads();
    if (tid < EMB_) {
        float s = b1[tid];
        #pragma unroll 8
        for (int j = 0; j < TT_*VEC_; j++) s += sflat[j]*W1[j*EMB_+tid];
        g_h[n*EMB_+tid] = tanhf(s);
    }
}

// ---------------- K2: batchnorm stats (deterministic, double accum) --------
__global__ void k_bnstats() {
    int col  = threadIdx.x / 32;   // 32 warps, one per column
    int lane = threadIdx.x % 32;
    double s = 0.0, s2 = 0.0;
    for (int r = lane; r < N_; r += 32) {
        double v = (double)g_h[r*EMB_+col];
        s += v; s2 += v*v;
    }
    for (int o = 16; o > 0; o >>= 1) {
        s  += __shfl_down_sync(0xffffffffu, s,  o);
        s2 += __shfl_down_sync(0xffffffffu, s2, o);
    }
    if (lane == 0) {
        double mu  = s / N_;
        double var = s2 / N_ - mu*mu;
        g_mu[col]   = (float)mu;
        g_rvar[col] = (float)(1.0 / sqrt(var + (double)EPS_));
    }
}

// ---------------- K3: emb + row sqnorms ------------------------------------
__global__ void k_emb(const float* __restrict__ gamma, const float* __restrict__ beta) {
    int warp = threadIdx.x / 32;
    int row  = blockIdx.x * (blockDim.x/32) + warp;
    int c    = threadIdx.x % 32;
    float e = gamma[c]*(g_h[row*EMB_+c]-g_mu[c])*g_rvar[c] + beta[c];
    g_emb[row*EMB_+c] = e;
    float q = e*e;
    for (int o = 16; o > 0; o >>= 1) q += __shfl_down_sync(0xffffffffu, q, o);
    if (c == 0) g_sqn[row] = q;
}

// ---------------- K4: D0 = exp(-dist/(2s^2)) tiles + off-diag partial sum --
__global__ void k_d0(const float* __restrict__ sigma_p) {
    __shared__ float Ei[64*33], Ej[64*33], si[64], sj[64];
    __shared__ float red[256];
    int it = blockIdx.y, jt = blockIdx.x;
    int tid = threadIdx.x;
    float sg = sigma_p[0];
    float inv2 = 1.f/(2.f*sg*sg);
    for (int idx = tid; idx < 64*32; idx += 256) {
        int r = idx / 32, k = idx % 32;
        Ei[r*33+k] = g_emb[((size_t)it*64+r)*32+k];
        Ej[r*33+k] = g_emb[((size_t)jt*64+r)*32+k];
    }
    if (tid < 64) { si[tid] = g_sqn[it*64+tid]; sj[tid] = g_sqn[jt*64+tid]; }
    __syncthreads();
    int tx = tid % 16, ty = tid / 16;
    int r0 = ty*4, c0 = tx*4;
    float acc[4][4] = {};
    #pragma unroll
    for (int k = 0; k < 32; k++) {
        float a[4], b[4];
        #pragma unroll
        for (int i = 0; i < 4; i++) a[i] = Ei[(r0+i)*33+k];
        #pragma unroll
        for (int j = 0; j < 4; j++) b[j] = Ej[(c0+j)*33+k];
        #pragma unroll
        for (int i = 0; i < 4; i++)
            #pragma unroll
            for (int j = 0; j < 4; j++) acc[i][j] += a[i]*b[j];
    }
    float tsum = 0.f;
    #pragma unroll
    for (int i = 0; i < 4; i++) {
        int gi = it*64 + r0 + i;
        #pragma unroll
        for (int j = 0; j < 4; j++) {
            int gj = jt*64 + c0 + j;
            float sq = si[r0+i] + sj[c0+j] - 2.f*acc[i][j];
            sq = fmaxf(sq, 0.f);
            float d = (sq > 0.f) ? sqrtf(sq) : 0.f;
            float v = expf(-d*inv2);
            g_D[(size_t)gi*N_ + gj] = v;
            if (gi != gj) tsum += v;
        }
    }
    red[tid] = tsum; __syncthreads();
    for (int o = 128; o > 0; o >>= 1) { if (tid < o) red[tid] += red[tid+o]; __syncthreads(); }
    if (tid == 0) g_dpart[blockIdx.y*gridDim.x + blockIdx.x] = red[0];
}

// ---------------- K5: avg --------------------------------------------------
__global__ void k_avg() {
    __shared__ double red[1024];
    int tid = threadIdx.x;
    double s = 0.0;
    for (int i = tid; i < 4096; i += 1024) s += (double)g_dpart[i];
    red[tid] = s; __syncthreads();
    for (int o = 512; o > 0; o >>= 1) { if (tid < o) red[tid] += red[tid+o]; __syncthreads(); }
    if (tid == 0) g_avg = (float)(red[0] / ((double)N_*(double)(N_-1)));
}

// ---------------- K6: threshold in place + per-block min/max (off-diag) ----
__global__ void k_thresh() {
    float avg = g_avg;
    size_t total = (size_t)N_*N_;
    float mn =  INFINITY, mx = -INFINITY;
    size_t stride = (size_t)gridDim.x*blockDim.x;
    for (size_t idx = (size_t)blockIdx.x*blockDim.x + threadIdx.x; idx < total; idx += stride) {
        float v = g_D[idx];
        float t = (v < avg) ? 0.f : v;
        g_D[idx] = t;
        int i = (int)(idx >> 12), j = (int)(idx & 4095);
        if (i != j) { mn = fminf(mn, t); mx = fmaxf(mx, t); }
    }
    __shared__ float rmn[256], rmx[256];
    int tid = threadIdx.x;
    rmn[tid] = mn; rmx[tid] = mx; __syncthreads();
    for (int o = 128; o > 0; o >>= 1) {
        if (tid < o) { rmn[tid] = fminf(rmn[tid], rmn[tid+o]); rmx[tid] = fmaxf(rmx[tid], rmx[tid+o]); }
        __syncthreads();
    }
    if (tid == 0) { g_pmin[blockIdx.x] = rmn[0]; g_pmax[blockIdx.x] = rmx[0]; }
}

// ---------------- K7: finish min/max ---------------------------------------
__global__ void k_mnmx() {
    __shared__ float rmn[1024], rmx[1024];
    int tid = threadIdx.x;
    rmn[tid] = g_pmin[tid]; rmx[tid] = g_pmax[tid]; __syncthreads();
    for (int o = 512; o > 0; o >>= 1) {
        if (tid < o) { rmn[tid] = fminf(rmn[tid], rmn[tid+o]); rmx[tid] = fmaxf(rmx[tid], rmx[tid+o]); }
        __syncthreads();
    }
    if (tid == 0) {
        float mn = rmn[0], mx = rmx[0];
        if (mx == mn) mx = mn + 1.f;
        g_mn = mn; g_scale = 1.f/(mx - mn);
    }
}

// ---------------- K8: write final D ----------------------------------------
__global__ void k_writeD(float* __restrict__ outD) {
    float mn = g_mn, sc = g_scale;
    size_t total = (size_t)N_*N_;
    size_t stride = (size_t)gridDim.x*blockDim.x;
    for (size_t idx = (size_t)blockIdx.x*blockDim.x + threadIdx.x; idx < total; idx += stride) {
        int i = (int)(idx >> 12), j = (int)(idx & 4095);
        outD[idx] = (i == j) ? 1.f : (g_D[idx] - mn)*sc;
    }
}

// ---------------- K9: GEMM1  U = L @ [Wp1 | Wq1 | Wa]  (M=167936,K=256,N=3x64)
__global__ void k_gemm1(const float* __restrict__ L, const float* __restrict__ Wp1,
                        const float* __restrict__ Wq1, const float* __restrict__ Wa) {
    int mt  = blockIdx.x;          // 0..2623
    int grp = blockIdx.y;          // 0..2
    const float* B = (grp == 0) ? Wp1 : ((grp == 1) ? Wq1 : Wa);
    __shared__ float As[16][68];
    __shared__ float Bs[16][68];
    int tid = threadIdx.x;         // 256
    int tx = tid % 16, ty = tid / 16;
    float acc[4][4] = {};
    const float* Ablk = L + (size_t)mt*64*LDIM_;
    int lm = tid / 4;
    int lk = (tid % 4)*4;
    int bk = tid / 16;
    int bc = (tid % 16)*4;
    for (int k0 = 0; k0 < LDIM_; k0 += 16) {
        float4 av = *(const float4*)(Ablk + (size_t)lm*LDIM_ + k0 + lk);
        As[lk+0][lm] = av.x; As[lk+1][lm] = av.y; As[lk+2][lm] = av.z; As[lk+3][lm] = av.w;
        float4 bv = *(const float4*)(B + (size_t)(k0+bk)*64 + bc);
        *(float4*)&Bs[bk][bc] = bv;
        __syncthreads();
        #pragma unroll
        for (int kk = 0; kk < 16; kk++) {
            float a[4], b[4];
            #pragma unroll
            for (int i = 0; i < 4; i++) a[i] = As[kk][ty*4+i];
            #pragma unroll
            for (int j = 0; j < 4; j++) b[j] = Bs[kk][tx*4+j];
            #pragma unroll
            for (int i = 0; i < 4; i++)
                #pragma unroll
                for (int j = 0; j < 4; j++) acc[i][j] += a[i]*b[j];
        }
        __syncthreads();
    }
    float* U = g_U + (size_t)(mt*64)*192 + grp*64;
    #pragma unroll
    for (int i = 0; i < 4; i++) {
        float4 v = make_float4(acc[i][0], acc[i][1], acc[i][2], acc[i][3]);
        *(float4*)(U + (size_t)(ty*4+i)*192 + tx*4) = v;
    }
}

// ---------------- K10: inactive-branch constants ---------------------------
__global__ void k_zconst(const float* __restrict__ bp1, const float* __restrict__ Wp2,
                         const float* __restrict__ bp2, const float* __restrict__ bq1,
                         const float* __restrict__ Wq2, const float* __restrict__ bq2) {
    __shared__ float yp[64], yq[64];
    int c = threadIdx.x;
    yp[c] = tanhf(bp1[c]); yq[c] = tanhf(bq1[c]);
    __syncthreads();
    float sp = bp2[c], sq = bq2[c];
    for (int j = 0; j < 64; j++) { sp += yp[j]*Wp2[j*64+c]; sq += yq[j]*Wq2[j*64+c]; }
    g_zconst[c]      = tanhf(sp);
    g_zconst[64+c]   = tanhf(sq);
}

// ---------------- K11: second layer + means + final_feature ----------------
__global__ void k_second(const int* __restrict__ C, const float* __restrict__ Pw,
                         const float* __restrict__ Nw,
                         const float* __restrict__ bp1, const float* __restrict__ Wp2,
                         const float* __restrict__ bp2,
                         const float* __restrict__ bq1, const float* __restrict__ Wq2,
                         const float* __restrict__ bq2,
                         const float* __restrict__ ba, float* __restrict__ outFF) {
    int n = blockIdx.x;
    __shared__ float sWp[64*64], sWq[64*64];
    __shared__ float ys[2][64];
    __shared__ float comb[3*64];
    __shared__ float sq4[8];
    int tid = threadIdx.x;   // 128
    for (int i = tid; i < 4096; i += 128) { sWp[i] = Wp2[i]; sWq[i] = Wq2[i]; }
    int start = C[2*n], end = C[2*n+1];
    int half = tid / 64, c = tid % 64;
    float accP = 0.f, accN = 0.f, accF = 0.f;
    float bpc = bp1[c], bqc = bq1[c], bac = ba[c];
    float z0p = bp2[c], z0q = bq2[c];
    __syncthreads();
    for (int sb = 0; sb < SEQ_; sb += 2) {
        int s = sb + half;
        bool valid = (s < SEQ_);
        bool inr = false; float w = 0.f; const float* base = nullptr;
        if (valid) {
            inr = (s >= start && s <= end);
            w = inr ? Pw[n*SEQ_+s] : Nw[n*SEQ_+s];
            base = g_U + (size_t)(n*SEQ_+s)*192;
            float u = base[(inr ? 0 : 64) + c];
            ys[half][c] = tanhf(w*u + (inr ? bpc : bqc));
        }
        __syncthreads();
        if (valid) {
            const float* W2 = inr ? sWp : sWq;
            float z = inr ? z0p : z0q;
            #pragma unroll 8
            for (int j = 0; j < 64; j++) z += ys[half][j]*W2[j*64+c];
            z = tanhf(z);
            if (inr) accP += z; else accN += z;
            accF += tanhf(w*base[128+c] + bac);
        }
        __syncthreads();
    }
    if (half == 0) { comb[c] = accP; comb[64+c] = accN; comb[128+c] = accF; }
    __syncthreads();
    if (half == 1) {
        float len = (float)(end - start + 1);
        float P = (comb[c]      + accP + ((float)SEQ_ - len)*g_zconst[c])      / (float)SEQ_;
        float Q = (comb[64+c]   + accN + len*g_zconst[64+c])                   / (float)SEQ_;
        float F = (comb[128+c]  + accF)                                        / (float)SEQ_;
        g_pos[n*64+c] = P; g_neg[n*64+c] = Q;
        outFF[n*64+c] = F;
        float p2 = P*P, q2 = Q*Q;
        for (int o = 16; o > 0; o >>= 1) {
            p2 += __shfl_down_sync(0xffffffffu, p2, o);
            q2 += __shfl_down_sync(0xffffffffu, q2, o);
        }
        if ((c & 31) == 0) { sq4[c>>5] = p2; sq4[4+(c>>5)] = q2; }
    }
    __syncthreads();
    if (tid == 0) { g_psqn[n] = sq4[0]+sq4[1]; g_nsqn[n] = sq4[4]+sq4[5]; }
}

// ---------------- K12: similarity sums: sum exp(-cdist(X,Y)) ---------------
// mode 0: X=g_pos, Y=g_pos -> g_spartA ; mode 1: X=g_pos, Y=g_neg -> g_spartB
// NOTE: all __device__ globals bound HERE, in device code (host cannot pass
// __device__ symbol addresses as kernel args — that was the R1 NaN).
__global__ void k_sim(int mode) {
    const float* __restrict__ X  = g_pos;
    const float* __restrict__ Y  = mode ? g_neg  : g_pos;
    const float* __restrict__ xs = g_psqn;
    const float* __restrict__ yn = mode ? g_nsqn : g_psqn;
    double* __restrict__ outpart = mode ? g_spartB : g_spartA;

    __shared__ float Xs[64*65], Ys[64*65], sx[64], sy[64];
    __shared__ double red[256];
    int it = blockIdx.y, jt = blockIdx.x, tid = threadIdx.x;
    for (int idx = tid; idx < 64*64; idx += 256) {
        int r = idx / 64, k = idx % 64;
        Xs[r*65+k] = X[((size_t)it*64+r)*64+k];
        Ys[r*65+k] = Y[((size_t)jt*64+r)*64+k];
    }
    if (tid < 64) { sx[tid] = xs[it*64+tid]; sy[tid] = yn[jt*64+tid]; }
    __syncthreads();
    int tx = tid % 16, ty = tid / 16;
    int r0 = ty*4, c0 = tx*4;
    float acc[4][4] = {};
    #pragma unroll 8
    for (int k = 0; k < 64; k++) {
        float a[4], b[4];
        #pragma unroll
        for (int i = 0; i < 4; i++) a[i] = Xs[(r0+i)*65+k];
        #pragma unroll
        for (int j = 0; j < 4; j++) b[j] = Ys[(c0+j)*65+k];
        #pragma unroll
        for (int i = 0; i < 4; i++)
            #pragma unroll
            for (int j = 0; j < 4; j++) acc[i][j] += a[i]*b[j];
    }
    float tsum = 0.f;
    #pragma unroll
    for (int i = 0; i < 4; i++)
        #pragma unroll
        for (int j = 0; j < 4; j++) {
            float sq = sx[r0+i] + sy[c0+j] - 2.f*acc[i][j];
            sq = fmaxf(sq, 0.f);
            float d = (sq > 0.f) ? sqrtf(sq) : 0.f;
            tsum += expf(-d);
        }
    red[tid] = (double)tsum; __syncthreads();
    for (int o = 128; o > 0; o >>= 1) { if (tid < o) red[tid] += red[tid+o]; __syncthreads(); }
    if (tid == 0) outpart[it*gridDim.x + jt] = red[0];
}

// ---------------- K13: contrastive loss ------------------------------------
__global__ void k_loss(float* __restrict__ outLoss) {
    __shared__ double redA[1024], redB[1024];
    int tid = threadIdx.x;
    double a = 0.0, b = 0.0;
    for (int i = tid; i < 4096; i += 1024) { a += g_spartA[i]; b += g_spartB[i]; }
    redA[tid] = a; redB[tid] = b; __syncthreads();
    for (int o = 512; o > 0; o >>= 1) {
        if (tid < o) { redA[tid] += redA[tid+o]; redB[tid] += redB[tid+o]; }
        __syncthreads();
    }
    if (tid == 0) outLoss[0] = (float)(-(log(redA[0]) - log(redB[0])));
}

// ---------------- launch ---------------------------------------------------
extern "C" void kernel_launch(void* const* d_in, const int* in_sizes, int n_in,
                              void* d_out, int out_size) {
    const float* A     = (const float*)d_in[0];
    const int*   C     = (const int*)  d_in[1];
    const float* L     = (const float*)d_in[2];
    const float* W1    = (const float*)d_in[3];
    const float* b1    = (const float*)d_in[4];
    const float* gamma = (const float*)d_in[5];
    const float* beta  = (const float*)d_in[6];
    const float* sigma = (const float*)d_in[7];
    const float* Pw    = (const float*)d_in[8];
    const float* Nw    = (const float*)d_in[9];
    const float* Wp1   = (const float*)d_in[10];
    const float* bp1   = (const float*)d_in[11];
    const float* Wp2   = (const float*)d_in[12];
    const float* bp2   = (const float*)d_in[13];
    const float* Wq1   = (const float*)d_in[14];
    const float* bq1   = (const float*)d_in[15];
    const float* Wq2   = (const float*)d_in[16];
    const float* bq2   = (const float*)d_in[17];
    const float* Wa    = (const float*)d_in[18];
    const float* ba    = (const float*)d_in[19];

    float* out   = (float*)d_out;
    float* outFF = out;                       // (N, 64)
    float* outL  = out + N_*RED_;             // scalar
    float* outD  = out + N_*RED_ + 1;         // (N, N)

    // embedding / D chain
    k_interp_h<<<N_, 128>>>(A, C, W1, b1);
    k_bnstats<<<1, 1024>>>();
    k_emb<<<512, 256>>>(gamma, beta);
    k_d0<<<dim3(64,64), 256>>>(sigma);
    k_avg<<<1, 1024>>>();
    k_thresh<<<1024, 256>>>();
    k_mnmx<<<1, 1024>>>();
    k_writeD<<<8192, 256>>>(outD);

    // L chain
    k_gemm1<<<dim3(2624, 3), 256>>>(L, Wp1, Wq1, Wa);
    k_zconst<<<1, 64>>>(bp1, Wp2, bp2, bq1, Wq2, bq2);
    k_second<<<N_, 128>>>(C, Pw, Nw, bp1, Wp2, bp2, bq1, Wq2, bq2, ba, outFF);
    k_sim<<<dim3(64,64), 256>>>(0);
    k_sim<<<dim3(64,64), 256>>>(1);
    k_loss<<<1, 1024>>>(outL);
}